// round 1
// baseline (speedup 1.0000x reference)
#include <cuda_runtime.h>
#include <cuda_bf16.h>

// Problem constants (fixed by the dataset)
#define NN   100000      // nodes
#define EE   1600000     // edges
#define DIN  128
#define DH   128
#define DOUT 64
#define CAP  128         // adjacency bucket capacity per node (Poisson(15)+1 max << 64)

// ---------------- scratch (device globals; no allocation allowed) ----------
__device__ float g_h0[(size_t)NN * DH];    // x @ W1
__device__ float g_h1[(size_t)NN * DH];    // relu(mean-agg(h0))
__device__ float g_h2[(size_t)NN * DOUT];  // h1 @ W2
__device__ int   g_deg[NN];
__device__ int   g_adj[(size_t)NN * CAP];

// ---------------- adjacency build ------------------------------------------
__global__ void k_clear_deg() {
    int i = blockIdx.x * blockDim.x + threadIdx.x;
    if (i < NN) g_deg[i] = 0;
}

__global__ void k_build_adj(const int* __restrict__ erow,
                            const int* __restrict__ ecol) {
    int e = blockIdx.x * blockDim.x + threadIdx.x;
    if (e >= EE) return;
    int r = erow[e];
    int c = ecol[e];
    int pos = atomicAdd(&g_deg[r], 1);
    if (pos < CAP) g_adj[(size_t)r * CAP + pos] = c;
}

// ---------------- GEMM: C[nrows, DO] = A[nrows, 128] @ W[128, DO] ----------
// 256 threads; TX = DO/4 threads across columns (TN=4), TY = 256/TX row groups,
// each thread computes TM rows x 4 cols. BM = TY*TM = 64 for both instantiations.
template <int DO, int TM>
__global__ void k_gemm(const float* __restrict__ A,
                       const float* __restrict__ W,
                       float* __restrict__ C, int nrows) {
    constexpr int DK = 128;
    constexpr int BK = 16;
    constexpr int TX = DO / 4;
    constexpr int TY = 256 / TX;
    constexpr int BM = TY * TM;
    static_assert(BM == 64, "tile mismatch");

    __shared__ float As[BK][BM];   // As[kk][row]
    __shared__ float Ws[BK][DO];   // Ws[kk][col]

    const int tid = threadIdx.x;
    const int tx = tid % TX;
    const int ty = tid / TX;
    const int r0 = blockIdx.x * BM;

    float acc[TM][4];
#pragma unroll
    for (int i = 0; i < TM; i++)
#pragma unroll
        for (int j = 0; j < 4; j++) acc[i][j] = 0.0f;

    // staging indices for As: one float4 per thread
    const int lr = tid >> 2;        // 0..63  (row within tile)
    const int kq = tid & 3;         // 0..3   (k quad within chunk)

    for (int kc = 0; kc < DK; kc += BK) {
        __syncthreads();  // protect previous iteration's reads

        // load W chunk: BK*DO contiguous floats starting at W + kc*DO
        const float4* wsrc = reinterpret_cast<const float4*>(W + kc * DO);
#pragma unroll
        for (int i = tid; i < BK * DO / 4; i += 256)
            reinterpret_cast<float4*>(&Ws[0][0])[i] = wsrc[i];

        // load A chunk transposed
        float4 av = make_float4(0.f, 0.f, 0.f, 0.f);
        int gr = r0 + lr;
        if (gr < nrows)
            av = *reinterpret_cast<const float4*>(A + (size_t)gr * DK + kc + kq * 4);
        As[kq * 4 + 0][lr] = av.x;
        As[kq * 4 + 1][lr] = av.y;
        As[kq * 4 + 2][lr] = av.z;
        As[kq * 4 + 3][lr] = av.w;

        __syncthreads();

#pragma unroll
        for (int kk = 0; kk < BK; kk++) {
            float a[TM];
#pragma unroll
            for (int i = 0; i < TM; i += 4) {
                float4 t = *reinterpret_cast<const float4*>(&As[kk][ty * TM + i]);
                a[i + 0] = t.x; a[i + 1] = t.y; a[i + 2] = t.z; a[i + 3] = t.w;
            }
            float4 wv = *reinterpret_cast<const float4*>(&Ws[kk][tx * 4]);
#pragma unroll
            for (int i = 0; i < TM; i++) {
                acc[i][0] = fmaf(a[i], wv.x, acc[i][0]);
                acc[i][1] = fmaf(a[i], wv.y, acc[i][1]);
                acc[i][2] = fmaf(a[i], wv.z, acc[i][2]);
                acc[i][3] = fmaf(a[i], wv.w, acc[i][3]);
            }
        }
    }

#pragma unroll
    for (int i = 0; i < TM; i++) {
        int r = r0 + ty * TM + i;
        if (r < nrows) {
            float4 v = make_float4(acc[i][0], acc[i][1], acc[i][2], acc[i][3]);
            *reinterpret_cast<float4*>(C + (size_t)r * DO + tx * 4) = v;
        }
    }
}

// ---------------- mean aggregation: warp per node ---------------------------
// dst[i] = (optionally relu)( (1/deg[i]) * sum_{j in adj[i]} src[j] )
template <int D, bool RELU>
__global__ void k_agg(const float* __restrict__ src, float* __restrict__ dst) {
    constexpr int VEC = D / 32;  // floats per lane (4 or 2)
    const int gw = (blockIdx.x * blockDim.x + threadIdx.x) >> 5;
    if (gw >= NN) return;
    const int lane = threadIdx.x & 31;

    const int d = g_deg[gw];
    const int cnt = d < CAP ? d : CAP;
    const int* __restrict__ adj = g_adj + (size_t)gw * CAP;

    float acc[VEC];
#pragma unroll
    for (int v = 0; v < VEC; v++) acc[v] = 0.0f;

#pragma unroll 4
    for (int t = 0; t < cnt; t++) {
        int j = __ldg(&adj[t]);
        const float* p = src + (size_t)j * D + lane * VEC;
        if (VEC == 4) {
            float4 v = *reinterpret_cast<const float4*>(p);
            acc[0] += v.x; acc[1] += v.y; acc[2] += v.z; acc[3] += v.w;
        } else {
            float2 v = *reinterpret_cast<const float2*>(p);
            acc[0] += v.x; acc[1] += v.y;
        }
    }

    const float inv = 1.0f / (float)d;  // divisor = true degree
    float* q = dst + (size_t)gw * D + lane * VEC;
    if (VEC == 4) {
        float4 o;
        o.x = acc[0] * inv; o.y = acc[1] * inv;
        o.z = acc[2] * inv; o.w = acc[3] * inv;
        if (RELU) {
            o.x = fmaxf(o.x, 0.f); o.y = fmaxf(o.y, 0.f);
            o.z = fmaxf(o.z, 0.f); o.w = fmaxf(o.w, 0.f);
        }
        *reinterpret_cast<float4*>(q) = o;
    } else {
        float2 o;
        o.x = acc[0] * inv; o.y = acc[1] * inv;
        if (RELU) { o.x = fmaxf(o.x, 0.f); o.y = fmaxf(o.y, 0.f); }
        *reinterpret_cast<float2*>(q) = o;
    }
}

// ---------------- launch -----------------------------------------------------
extern "C" void kernel_launch(void* const* d_in, const int* in_sizes, int n_in,
                              void* d_out, int out_size) {
    const float* x    = (const float*)d_in[0];
    const float* W1   = (const float*)d_in[1];
    const float* W2   = (const float*)d_in[2];
    const int*   erow = (const int*)d_in[3];
    const int*   ecol = (const int*)d_in[4];
    float* out = (float*)d_out;

    // adjacency (built each call; deterministic work)
    k_clear_deg<<<(NN + 255) / 256, 256>>>();
    k_build_adj<<<(EE + 255) / 256, 256>>>(erow, ecol);

    // layer 1: h0 = x @ W1 ; h1 = relu(mean_agg(h0))
    float* h0 = nullptr; float* h1 = nullptr; float* h2 = nullptr;
    // device-symbol addresses via kernel-side globals: use cudaGetSymbolAddress-free
    // approach — kernels reference the globals directly, GEMM writes via pointer:
    // get raw pointers with cudaGetSymbolAddress is a host call; instead pass
    // through small helper kernels is overkill. Use cudaGetSymbolAddress (not an
    // allocation; capture-safe, executes immediately).
    cudaGetSymbolAddress((void**)&h0, g_h0);
    cudaGetSymbolAddress((void**)&h1, g_h1);
    cudaGetSymbolAddress((void**)&h2, g_h2);

    k_gemm<128, 8><<<(NN + 63) / 64, 256>>>(x, W1, h0, NN);
    k_agg<128, true><<<(NN * 32 + 255) / 256, 256>>>(h0, h1);

    // layer 2: h2 = h1 @ W2 ; out = mean_agg(h2)
    k_gemm<64, 4><<<(NN + 63) / 64, 256>>>(h1, W2, h2, NN);
    k_agg<64, false><<<(NN * 32 + 255) / 256, 256>>>(h2, out);
}